// round 4
// baseline (speedup 1.0000x reference)
#include <cuda_runtime.h>
#include <cstdint>

// Zero-initialized device globals (no allocations allowed).
// g_flags bit0: any(((x+1)+1) >= 3)   -> chain halts at checker #1; speculative out is correct
// g_flags bit1: any(four-adds >= 3)   -> chain halts at checker #2
// Last-arriving block performs (never-taken) fixup and resets both globals,
// keeping every graph replay deterministic.
__device__ int g_flags;
__device__ unsigned int g_count;

__global__ void __launch_bounds__(512) scn_fused_kernel(
    const float4* __restrict__ x, float4* __restrict__ out, int n4)
{
    const int idx    = blockIdx.x * blockDim.x + threadIdx.x;
    const int stride = gridDim.x * blockDim.x;

    // Running max of o = (x+1)+1 over all elements this thread touches.
    float m = -3.402823466e+38f;

    int i = idx;
    const int stride4 = stride * 4;

    // Unrolled-by-4 main loop: 4 independent LDG.128 front-batched per iteration.
    for (; i + 3 * stride < n4; i += stride4) {
        float4 v0 = __ldcs(&x[i]);
        float4 v1 = __ldcs(&x[i + stride]);
        float4 v2 = __ldcs(&x[i + 2 * stride]);
        float4 v3 = __ldcs(&x[i + 3 * stride]);

        float4 o0, o1, o2, o3;
        o0.x = (v0.x + 1.0f) + 1.0f;  o0.y = (v0.y + 1.0f) + 1.0f;
        o0.z = (v0.z + 1.0f) + 1.0f;  o0.w = (v0.w + 1.0f) + 1.0f;
        o1.x = (v1.x + 1.0f) + 1.0f;  o1.y = (v1.y + 1.0f) + 1.0f;
        o1.z = (v1.z + 1.0f) + 1.0f;  o1.w = (v1.w + 1.0f) + 1.0f;
        o2.x = (v2.x + 1.0f) + 1.0f;  o2.y = (v2.y + 1.0f) + 1.0f;
        o2.z = (v2.z + 1.0f) + 1.0f;  o2.w = (v2.w + 1.0f) + 1.0f;
        o3.x = (v3.x + 1.0f) + 1.0f;  o3.y = (v3.y + 1.0f) + 1.0f;
        o3.z = (v3.z + 1.0f) + 1.0f;  o3.w = (v3.w + 1.0f) + 1.0f;

        float ma = fmaxf(fmaxf(o0.x, o0.y), fmaxf(o0.z, o0.w));
        float mb = fmaxf(fmaxf(o1.x, o1.y), fmaxf(o1.z, o1.w));
        float mc = fmaxf(fmaxf(o2.x, o2.y), fmaxf(o2.z, o2.w));
        float md = fmaxf(fmaxf(o3.x, o3.y), fmaxf(o3.z, o3.w));
        m = fmaxf(m, fmaxf(fmaxf(ma, mb), fmaxf(mc, md)));

        __stcs(&out[i],              o0);
        __stcs(&out[i + stride],     o1);
        __stcs(&out[i + 2 * stride], o2);
        __stcs(&out[i + 3 * stride], o3);
    }

    // Tail.
    for (; i < n4; i += stride) {
        float4 v = __ldcs(&x[i]);
        float4 o;
        o.x = (v.x + 1.0f) + 1.0f;  o.y = (v.y + 1.0f) + 1.0f;
        o.z = (v.z + 1.0f) + 1.0f;  o.w = (v.w + 1.0f) + 1.0f;
        m = fmaxf(m, fmaxf(fmaxf(o.x, o.y), fmaxf(o.z, o.w)));
        __stcs(&out[i], o);
    }

    // fp add of a constant is monotone non-decreasing, so:
    //   any((o+1)+1 >= 3)  <=>  ((max(o)+1)+1) >= 3   (bit-exact)
    bool a = (m >= 3.0f);
    bool b = (((m + 1.0f) + 1.0f) >= 3.0f);

    int any_a = __syncthreads_or(a ? 1 : 0);
    int any_b = __syncthreads_or(b ? 1 : 0);

    // Make this block's out[] writes device-visible before signalling arrival.
    __threadfence();
    __syncthreads();

    __shared__ int s_last;
    if (threadIdx.x == 0) {
        int f = (any_a ? 1 : 0) | (any_b ? 2 : 0);
        if (f) atomicOr(&g_flags, f);
        __threadfence();
        unsigned t = atomicAdd(&g_count, 1u);
        s_last = (t == gridDim.x - 1) ? 1 : 0;
    }
    __syncthreads();

    if (s_last) {
        int f = atomicOr(&g_flags, 0);

        if (!(f & 1)) {
            // Rare path (statistically never for this input): chain survived
            // checker #1 — rewrite output with the deeper-chain values.
            bool five = !(f & 2);
            for (int j = threadIdx.x; j < n4; j += blockDim.x) {
                float4 v = x[j];
                float4 o;
                o.x = (((v.x + 1.0f) + 1.0f) + 1.0f) + 1.0f;
                o.y = (((v.y + 1.0f) + 1.0f) + 1.0f) + 1.0f;
                o.z = (((v.z + 1.0f) + 1.0f) + 1.0f) + 1.0f;
                o.w = (((v.w + 1.0f) + 1.0f) + 1.0f) + 1.0f;
                if (five) { o.x += 1.0f; o.y += 1.0f; o.z += 1.0f; o.w += 1.0f; }
                out[j] = o;
            }
        }

        __syncthreads();
        if (threadIdx.x == 0) {
            g_flags = 0;
            __threadfence();
            g_count = 0u;
        }
    }
}

extern "C" void kernel_launch(void* const* d_in, const int* in_sizes, int n_in,
                              void* d_out, int out_size)
{
    const float4* x = (const float4*)d_in[0];
    float4* out = (float4*)d_out;
    int n = in_sizes[0];
    int n4 = n >> 2;  // 4096*8192 divisible by 4

    const int threads = 512;
    const int blocks  = 148 * 4;  // one full wave at 2048 thr/SM

    scn_fused_kernel<<<blocks, threads>>>(x, out, n4);
}

// round 6
// speedup vs baseline: 1.0559x; 1.0559x over previous
#include <cuda_runtime.h>
#include <cstdint>

// Zero-initialized device globals (no allocations allowed).
// g_flags bit0: any(((x+1)+1) >= 3)   -> chain halts at checker #1; speculative out is correct
// g_flags bit1: any(four-adds >= 3)   -> chain halts at checker #2
// Last-arriving block performs the (statistically never-taken) fixup and
// resets both globals so every graph replay is deterministic.
__device__ int g_flags;
__device__ unsigned int g_count;

#define THREADS 512
#define UNROLL  8
#define CHUNK   (THREADS * UNROLL)   // 4096 float4 = 64 KB per block-iteration

__global__ void __launch_bounds__(THREADS, 2) scn_fused_kernel(
    const float4* __restrict__ x, float4* __restrict__ out, int n4)
{
    const int t = threadIdx.x;

    // Running max of o = (x+1)+1 over this thread's elements.
    float m = -3.402823466e+38f;

    const int nchunks = n4 / CHUNK;           // 8388608 / 4096 = 2048 (exact)

    for (int c = blockIdx.x; c < nchunks; c += gridDim.x) {
        const int base = c * CHUNK + t;

        // 8 independent coalesced LDG.128, all within one dense 64 KB chunk.
        float4 v[UNROLL];
#pragma unroll
        for (int k = 0; k < UNROLL; k++)
            v[k] = x[base + k * THREADS];

        float4 o[UNROLL];
#pragma unroll
        for (int k = 0; k < UNROLL; k++) {
            o[k].x = (v[k].x + 1.0f) + 1.0f;
            o[k].y = (v[k].y + 1.0f) + 1.0f;
            o[k].z = (v[k].z + 1.0f) + 1.0f;
            o[k].w = (v[k].w + 1.0f) + 1.0f;
            m = fmaxf(m, fmaxf(fmaxf(o[k].x, o[k].y), fmaxf(o[k].z, o[k].w)));
        }

#pragma unroll
        for (int k = 0; k < UNROLL; k++)
            out[base + k * THREADS] = o[k];
    }

    // Generic tail (empty for this shape, kept for correctness).
    for (int i = nchunks * CHUNK + blockIdx.x * THREADS + t; i < n4;
         i += gridDim.x * THREADS) {
        float4 v = x[i];
        float4 o;
        o.x = (v.x + 1.0f) + 1.0f;  o.y = (v.y + 1.0f) + 1.0f;
        o.z = (v.z + 1.0f) + 1.0f;  o.w = (v.w + 1.0f) + 1.0f;
        m = fmaxf(m, fmaxf(fmaxf(o.x, o.y), fmaxf(o.z, o.w)));
        out[i] = o;
    }

    // fp add of a constant is monotone non-decreasing, so (bit-exact):
    //   any((o+1)+1 >= 3)  <=>  ((max(o)+1)+1) >= 3
    bool a = (m >= 3.0f);
    bool b = (((m + 1.0f) + 1.0f) >= 3.0f);

    int any_a = __syncthreads_or(a ? 1 : 0);
    int any_b = __syncthreads_or(b ? 1 : 0);

    // Make this block's out[] writes device-visible before signalling arrival.
    __threadfence();
    __syncthreads();

    __shared__ int s_last;
    if (t == 0) {
        int f = (any_a ? 1 : 0) | (any_b ? 2 : 0);
        if (f) atomicOr(&g_flags, f);
        __threadfence();
        unsigned cnt = atomicAdd(&g_count, 1u);
        s_last = (cnt == gridDim.x - 1) ? 1 : 0;
    }
    __syncthreads();

    if (s_last) {
        int f = atomicOr(&g_flags, 0);

        if (!(f & 1)) {
            // Rare path (statistically never for this input): the chain
            // survived checker #1 — rewrite output with deeper-chain values.
            bool five = !(f & 2);
            for (int j = t; j < n4; j += THREADS) {
                float4 v = x[j];
                float4 o;
                o.x = (((v.x + 1.0f) + 1.0f) + 1.0f) + 1.0f;
                o.y = (((v.y + 1.0f) + 1.0f) + 1.0f) + 1.0f;
                o.z = (((v.z + 1.0f) + 1.0f) + 1.0f) + 1.0f;
                o.w = (((v.w + 1.0f) + 1.0f) + 1.0f) + 1.0f;
                if (five) { o.x += 1.0f; o.y += 1.0f; o.z += 1.0f; o.w += 1.0f; }
                out[j] = o;
            }
        }

        __syncthreads();
        if (t == 0) {
            g_flags = 0;
            __threadfence();
            g_count = 0u;
        }
    }
}

extern "C" void kernel_launch(void* const* d_in, const int* in_sizes, int n_in,
                              void* d_out, int out_size)
{
    const float4* x = (const float4*)d_in[0];
    float4* out = (float4*)d_out;
    int n = in_sizes[0];
    int n4 = n >> 2;  // 4096*8192 divisible by 4

    const int blocks = 148 * 4;  // 2 resident blocks/SM (launch_bounds), 2 waves
    scn_fused_kernel<<<blocks, THREADS>>>(x, out, n4);
}